// round 12
// baseline (speedup 1.0000x reference)
#include <cuda_runtime.h>
#include <cuda_fp16.h>
#include <math.h>

// Problem dims (fixed by the reference)
#define Dh     256
#define Qn     64
#define Pn     128
#define Bn     64
#define TWO_D  512
#define FOUR_D 1024
#define LDW    33280   // (Q+1)*2D, row stride of W_ih

// ---------------- scratch (device globals: no allocation allowed) ----------------
__device__ float d_Spre[Pn * Bn * Dh];            //  8 MB
__device__ float d_Gp  [Pn * Bn * FOUR_D];        // 32 MB (+ b_ih+b_hh)
__device__ float d_bsum[FOUR_D];

// fp16 packed recurrent streams
__device__ uint4 d_ga4 [Bn * Qn * Dh / 8];        //  2 MB  gah[b][q][d]
__device__ uint4 d_Wh4 [64 * 512];                // 512 KB Wh4[e4][jp][..]
__device__ uint2 d_Wb4 [64 * 256];                // 128 KB Wb4[e4][d][4e]
__device__ uint4 d_U4  [Bn * 16 * 512];           //  8 MB  U4[b][q4][jp][..]

__device__ __forceinline__ float2 h22f2(unsigned u) {
    __half2 h = *reinterpret_cast<__half2*>(&u);
    return __half22float2(h);
}
__device__ __forceinline__ __half2 u2h2(unsigned u) {
    return *reinterpret_cast<__half2*>(&u);
}
__device__ __forceinline__ float tanh_a(float x) {
    float y; asm("tanh.approx.f32 %0, %1;" : "=f"(y) : "f"(x)); return y;
}

// ---------------- cluster helpers (proven pattern) ----------------
__device__ __forceinline__ unsigned smem_u32(const void* p) {
    unsigned a;
    asm("{ .reg .u64 t; cvta.to.shared.u64 t, %1; cvt.u32.u64 %0, t; }"
        : "=r"(a) : "l"(p));
    return a;
}
__device__ __forceinline__ unsigned mapa_u32(unsigned addr, unsigned rank) {
    unsigned r;
    asm("mapa.shared::cluster.u32 %0, %1, %2;" : "=r"(r) : "r"(addr), "r"(rank));
    return r;
}
__device__ __forceinline__ void stc_f32(unsigned addr, float v) {
    asm volatile("st.shared::cluster.f32 [%0], %1;" :: "r"(addr), "f"(v) : "memory");
}
__device__ __forceinline__ void stc_f32x2(unsigned addr, float v0, float v1) {
    asm volatile("st.shared::cluster.v2.f32 [%0], {%1, %2};"
                 :: "r"(addr), "f"(v0), "f"(v1) : "memory");
}
__device__ __forceinline__ unsigned ctarank_u32() {
    unsigned r; asm("mov.u32 %0, %%cluster_ctarank;" : "=r"(r)); return r;
}
#define CLUSTER_SYNC() do {                                          \
    asm volatile("barrier.cluster.arrive.aligned;" ::: "memory");    \
    asm volatile("barrier.cluster.wait.aligned;"   ::: "memory");    \
} while (0)

// ---------------- GEMM 64x64 body (proven) ----------------
__device__ __forceinline__ void gemm64_body(
    int m0, int n0,
    const float* __restrict__ A, int lda,
    const float* __restrict__ Bm, int ldb,
    float acc[4][4], int tid)
{
    __shared__ float As64[16][68];
    __shared__ float Bs64[16][68];
    const int tx = tid & 15;
    const int ty = tid >> 4;
    const int lr = tid >> 2;
    const int lk = (tid & 3) * 4;

#pragma unroll
    for (int i = 0; i < 4; i++)
#pragma unroll
        for (int j = 0; j < 4; j++) acc[i][j] = 0.f;

    for (int k0 = 0; k0 < 512; k0 += 16) {
        float4 a4 = *(const float4*)&A [(long)(m0 + lr) * lda + k0 + lk];
        float4 b4 = *(const float4*)&Bm[(long)(n0 + lr) * ldb + k0 + lk];
        __syncthreads();
        As64[lk + 0][lr] = a4.x; As64[lk + 1][lr] = a4.y;
        As64[lk + 2][lr] = a4.z; As64[lk + 3][lr] = a4.w;
        Bs64[lk + 0][lr] = b4.x; Bs64[lk + 1][lr] = b4.y;
        Bs64[lk + 2][lr] = b4.z; Bs64[lk + 3][lr] = b4.w;
        __syncthreads();
#pragma unroll
        for (int kk = 0; kk < 16; kk++) {
            float4 av = *(const float4*)&As64[kk][ty * 4];
            float4 bv = *(const float4*)&Bs64[kk][tx * 4];
            acc[0][0] += av.x * bv.x; acc[0][1] += av.x * bv.y;
            acc[0][2] += av.x * bv.z; acc[0][3] += av.x * bv.w;
            acc[1][0] += av.y * bv.x; acc[1][1] += av.y * bv.y;
            acc[1][2] += av.y * bv.z; acc[1][3] += av.y * bv.w;
            acc[2][0] += av.z * bv.x; acc[2][1] += av.z * bv.y;
            acc[2][2] += av.z * bv.z; acc[2][3] += av.z * bv.w;
            acc[3][0] += av.w * bv.x; acc[3][1] += av.w * bv.y;
            acc[3][2] += av.w * bv.z; acc[3][3] += av.w * bv.w;
        }
    }
}

// ---------------- GEMM 128x128 body, 8x8 per thread (fp32) ----------------------
__device__ __forceinline__ void gemm128x128_body(
    int m0, int n0,
    const float* __restrict__ A, int lda,
    const float* __restrict__ Bm, int ldb,
    float* __restrict__ C, int ldc, const float* __restrict__ bias, int tid)
{
    __shared__ float As[16][132];
    __shared__ float Bs[16][132];
    const int tx = tid & 15;
    const int ty = tid >> 4;
    const int lrow = tid >> 1;
    const int lk   = (tid & 1) * 8;

    float acc[8][8];
#pragma unroll
    for (int i = 0; i < 8; i++)
#pragma unroll
        for (int j = 0; j < 8; j++) acc[i][j] = 0.f;

    for (int k0 = 0; k0 < 512; k0 += 16) {
        float4 a0 = *(const float4*)&A [(long)(m0 + lrow) * lda + k0 + lk];
        float4 a1 = *(const float4*)&A [(long)(m0 + lrow) * lda + k0 + lk + 4];
        float4 b0 = *(const float4*)&Bm[(long)(n0 + lrow) * ldb + k0 + lk];
        float4 b1 = *(const float4*)&Bm[(long)(n0 + lrow) * ldb + k0 + lk + 4];
        __syncthreads();
        As[lk + 0][lrow] = a0.x; As[lk + 1][lrow] = a0.y;
        As[lk + 2][lrow] = a0.z; As[lk + 3][lrow] = a0.w;
        As[lk + 4][lrow] = a1.x; As[lk + 5][lrow] = a1.y;
        As[lk + 6][lrow] = a1.z; As[lk + 7][lrow] = a1.w;
        Bs[lk + 0][lrow] = b0.x; Bs[lk + 1][lrow] = b0.y;
        Bs[lk + 2][lrow] = b0.z; Bs[lk + 3][lrow] = b0.w;
        Bs[lk + 4][lrow] = b1.x; Bs[lk + 5][lrow] = b1.y;
        Bs[lk + 6][lrow] = b1.z; Bs[lk + 7][lrow] = b1.w;
        __syncthreads();
#pragma unroll
        for (int kk = 0; kk < 16; kk++) {
            float4 av0 = *(const float4*)&As[kk][ty * 8];
            float4 av1 = *(const float4*)&As[kk][ty * 8 + 4];
            float4 bv0 = *(const float4*)&Bs[kk][tx * 8];
            float4 bv1 = *(const float4*)&Bs[kk][tx * 8 + 4];
            float a_[8] = {av0.x, av0.y, av0.z, av0.w, av1.x, av1.y, av1.z, av1.w};
            float b_[8] = {bv0.x, bv0.y, bv0.z, bv0.w, bv1.x, bv1.y, bv1.z, bv1.w};
#pragma unroll
            for (int i = 0; i < 8; i++)
#pragma unroll
                for (int j = 0; j < 8; j++)
                    acc[i][j] += a_[i] * b_[j];
        }
    }

    float bb[8];
#pragma unroll
    for (int j = 0; j < 8; j++) bb[j] = bias ? bias[n0 + tx * 8 + j] : 0.f;
#pragma unroll
    for (int i = 0; i < 8; i++) {
        long row = m0 + ty * 8 + i;
        float4 o0, o1;
        o0.x = acc[i][0] + bb[0]; o0.y = acc[i][1] + bb[1];
        o0.z = acc[i][2] + bb[2]; o0.w = acc[i][3] + bb[3];
        o1.x = acc[i][4] + bb[4]; o1.y = acc[i][5] + bb[5];
        o1.z = acc[i][6] + bb[6]; o1.w = acc[i][7] + bb[7];
        *(float4*)&C[row * ldc + n0 + tx * 8]     = o0;
        *(float4*)&C[row * ldc + n0 + tx * 8 + 4] = o1;
    }
}

// ---------------- front kernel: prep + ga + spre ----------------
__global__ void __launch_bounds__(256)
k_front(const float* __restrict__ b_ih, const float* __restrict__ b_hh,
        const float* __restrict__ W_hh, const float* __restrict__ Wb,
        const float* __restrict__ H_q,  const float* __restrict__ Wg,
        const float* __restrict__ H_p,  const float* __restrict__ Wa,
        const float* __restrict__ ba)
{
    const int bx = blockIdx.x;
    const int tid = threadIdx.x;

    if (bx < 256) {
        int idx = bx * 256 + tid;
        {
            int e4 = idx & 63, j = idx >> 6;
            float4 w = *(const float4*)&W_hh[j * Dh + e4 * 4];
            __half2 h01 = __floats2half2_rn(w.x, w.y);
            __half2 h23 = __floats2half2_rn(w.z, w.w);
            uint2 v;
            v.x = *reinterpret_cast<unsigned*>(&h01);
            v.y = *reinterpret_cast<unsigned*>(&h23);
            ((uint2*)d_Wh4)[e4 * 1024 + j] = v;
        }
        if (idx < 16384) {
            int e4 = idx & 63, d = idx >> 6;
            float4 w = *(const float4*)&Wb[d * Dh + e4 * 4];
            __half2 h01 = __floats2half2_rn(w.x, w.y);
            __half2 h23 = __floats2half2_rn(w.z, w.w);
            uint2 v;
            v.x = *reinterpret_cast<unsigned*>(&h01);
            v.y = *reinterpret_cast<unsigned*>(&h23);
            d_Wb4[e4 * 256 + d] = v;
        }
        if (idx < FOUR_D) d_bsum[idx] = b_ih[idx] + b_hh[idx];
    } else if (bx < 512) {
        const int t = bx - 256;
        const int n0 = (t & 3) * 64, m0 = (t >> 2) * 64;
        float acc[4][4];
        gemm64_body(m0, n0, H_q, TWO_D, Wg, TWO_D, acc, tid);
        __half* gah = (__half*)d_ga4;
        const int tx = tid & 15, ty = tid >> 4;
#pragma unroll
        for (int i = 0; i < 4; i++) {
            int m = m0 + ty * 4 + i;       // m = q*64 + b
            int q = m >> 6, b = m & 63;
            __half2 p01 = __floats2half2_rn(acc[i][0], acc[i][1]);
            __half2 p23 = __floats2half2_rn(acc[i][2], acc[i][3]);
            uint2 v;
            v.x = *reinterpret_cast<unsigned*>(&p01);
            v.y = *reinterpret_cast<unsigned*>(&p23);
            *(uint2*)&gah[((b * Qn + q) * Dh) + n0 + tx * 4] = v;
        }
    } else {
        const int t = bx - 512;
        const int n0 = (t & 1) * 128, m0 = (t >> 1) * 128;
        gemm128x128_body(m0, n0, H_p, TWO_D, Wa, TWO_D, d_Spre, Dh, ba, tid);
    }
}

__global__ void __launch_bounds__(256)
k_gemm_gp(const float* __restrict__ H_p, const float* __restrict__ W_ih) {
    gemm128x128_body(blockIdx.y * 128, blockIdx.x * 128,
                     H_p, TWO_D, W_ih, LDW, d_Gp, FOUR_D, d_bsum, threadIdx.x);
}

__global__ void __launch_bounds__(256)
k_gemm_u(const float* __restrict__ Aq, const float* __restrict__ W_ih) {
    const int q = blockIdx.z;
    const int m0 = 0, n0 = blockIdx.x * 64;
    float acc[4][4];
    gemm64_body(m0, n0, Aq + (long)q * Bn * TWO_D, TWO_D,
                W_ih + TWO_D + (long)q * TWO_D, LDW, acc, threadIdx.x);
    __half* U4h = (__half*)d_U4;
    const int tx = threadIdx.x & 15, ty = threadIdx.x >> 4;
    const int q4 = q >> 2, qp = q & 3;
#pragma unroll
    for (int i = 0; i < 4; i++) {
        int b = m0 + ty * 4 + i;
#pragma unroll
        for (int jj = 0; jj < 4; jj++) {
            long hidx = ((long)(b * 16 + q4) * FOUR_D + n0 + tx * 4 + jj) * 4 + qp;
            U4h[hidx] = __float2half_rn(acc[i][jj]);
        }
    }
}

// ---------------- sequential MatchLSTM: 2-CTA cluster, 512 threads/CTA ----------
//  phase 1: 4-way e-split (s_part[4][128]);
//  phase 2: 16 warps x 4 q;
//  phase 4: K-split — kq=0 does Wh e4 0..31, kq=1 does Wh e4 32..63 + U·alpha;
//           partials combined by tid<256 which adds Gp and sends to peer.
__device__ __forceinline__ float sigmoidf_(float x) { return 1.f / (1.f + expf(-x)); }

__global__ __launch_bounds__(512, 1) __cluster_dims__(2, 1, 1)
void seq_kernel(const float* __restrict__ h0,
                const float* __restrict__ c0,
                const float* __restrict__ alpha_w,
                const float* __restrict__ alpha_b,
                float* __restrict__ out)
{
    __shared__ __align__(16) float  h_s[Dh];
    __shared__ __align__(16) __half h_h[Dh];
    __shared__ __align__(16) float  c_s[Dh];
    __shared__ __align__(16) float  s_s[128];
    __shared__ __align__(16) float  s_part[4][128];
    __shared__ __align__(16) float  gates_s[FOUR_D];
    __shared__ __align__(16) float2 gpart[2][256];
    __shared__ __align__(16) float  logit_part[2][Qn];
    __shared__ __align__(16) float  alpha_s[Qn];
    __shared__ __align__(16) float  aw_s[Dh];

    const int tid  = threadIdx.x;
    const int warp = tid >> 5;
    const int lane = tid & 31;
    const unsigned rank = ctarank_u32();
    const unsigned peer = 1u - rank;
    const int r = (int)rank;
    const int b = blockIdx.x >> 1;
    const float ab = alpha_b[0];

    const unsigned gates_peer = mapa_u32(smem_u32(gates_s), peer);
    const unsigned logit_peer = mapa_u32(smem_u32(&logit_part[r][0]), peer);

    const __half* gah = (const __half*)d_ga4 + (long)b * Qn * Dh;
    const uint4*  u4b = d_U4 + (long)b * 16 * 512;
    const __half2 h2z = __float2half2_rn(0.f);
    const int tl = tid & 255;               // 0..255
    const int kq = tid >> 8;                // 0 or 1 (phase-4 K-half)
    const int jp = r * 256 + tl;            // phase-4 column pair

    if (tid < Dh) {
        aw_s[tid] = alpha_w[tid];
        float hv0 = h0[b * Dh + tid];
        h_s[tid] = hv0;
        h_h[tid] = __float2half_rn(hv0);
        c_s[tid] = c0[b * Dh + tid];
    }
    CLUSTER_SYNC();

    for (int t = 0; t < Pn; t++) {
        // ---- step-top prefetch (state-independent; consumed late) ----
        float2 gp_pre = make_float2(0.f, 0.f);
        if (tid < 256)
            gp_pre = *(const float2*)&d_Gp[((long)(t * Bn + b)) * FOUR_D + 2 * jp];
        float spre_pre = 0.f;
        if (tid < 128)
            spre_pre = d_Spre[((long)(t * Bn + b)) * Dh + 128 * r + tid];

        // ---- phase 1: s partials, 4-way e-split; thread (ec, dd) ----
        {
            const int dd = tid & 127, ec = tid >> 7;   // ec in {0..3}
            const int d = 128 * r + dd;
            const uint2* wb  = d_Wb4 + (long)(ec * 16) * 256 + d;
            const uint2* hhp = (const uint2*)h_h + ec * 16;
            float accf = 0.f;
            __half2 aA = h2z, aB = h2z;
#pragma unroll
            for (int i = 0; i < 8; i++) {
                uint2 wA = wb[i * 256],      wB = wb[(i + 8) * 256];
                uint2 hA = hhp[i],           hB = hhp[i + 8];
                aA = __hfma2(u2h2(wA.x), u2h2(hA.x), aA);
                aA = __hfma2(u2h2(wA.y), u2h2(hA.y), aA);
                aB = __hfma2(u2h2(wB.x), u2h2(hB.x), aB);
                aB = __hfma2(u2h2(wB.y), u2h2(hB.y), aB);
            }
            float2 fA = __half22float2(aA);
            float2 fB = __half22float2(aB);
            accf = (fA.x + fA.y) + (fB.x + fB.y);
            s_part[ec][dd] = accf;
        }
        __syncthreads();
        if (tid < 128)
            s_s[tid] = spre_pre + (s_part[0][tid] + s_part[1][tid])
                                + (s_part[2][tid] + s_part[3][tid]);
        __syncthreads();

        // ---- phase 2: partial logits; 16 warps x 4 q, gah hoisted ----
        {
            const int dl = lane * 4;
            const int dg = 128 * r + dl;
            uint2 gq[4];
#pragma unroll
            for (int qi = 0; qi < 4; qi++)
                gq[qi] = *(const uint2*)&gah[(long)(warp * 4 + qi) * Dh + dg];
            const float s0 = s_s[dl], s1 = s_s[dl + 1],
                        s2 = s_s[dl + 2], s3 = s_s[dl + 3];
            const float w0 = aw_s[dg], w1 = aw_s[dg + 1],
                        w2 = aw_s[dg + 2], w3 = aw_s[dg + 3];
#pragma unroll
            for (int qi = 0; qi < 4; qi++) {
                const int q = warp * 4 + qi;
                float2 g0 = h22f2(gq[qi].x), g1 = h22f2(gq[qi].y);
                float sum = tanh_a(g0.x + s0) * w0 + tanh_a(g0.y + s1) * w1 +
                            tanh_a(g1.x + s2) * w2 + tanh_a(g1.y + s3) * w3;
#pragma unroll
                for (int o = 16; o > 0; o >>= 1)
                    sum += __shfl_xor_sync(0xffffffffu, sum, o);
                if (lane == 0) {
                    logit_part[r][q] = sum;
                    stc_f32(logit_peer + q * 4, sum);
                }
            }
        }
        CLUSTER_SYNC();   // #1: partial logits visible in both CTAs

        // ---- phase 3: redundant softmax over 64 q (warp 0) ----
        if (warp == 0) {
            float l0 = logit_part[0][lane]      + logit_part[1][lane]      + ab;
            float l1 = logit_part[0][lane + 32] + logit_part[1][lane + 32] + ab;
            float m = fmaxf(l0, l1);
#pragma unroll
            for (int o = 16; o > 0; o >>= 1)
                m = fmaxf(m, __shfl_xor_sync(0xffffffffu, m, o));
            float e0 = expf(l0 - m), e1 = expf(l1 - m);
            float ssum = e0 + e1;
#pragma unroll
            for (int o = 16; o > 0; o >>= 1)
                ssum += __shfl_xor_sync(0xffffffffu, ssum, o);
            float inv = 1.f / ssum;
            alpha_s[lane]      = e0 * inv;
            alpha_s[lane + 32] = e1 * inv;
        }
        __syncthreads();

        // ---- phase 4: gate partials; kq selects K-half ----
        {
            float g0 = 0.f, g1 = 0.f;
            const uint2* hhp = (const uint2*)h_h;
            const int e4base = kq * 32;
            __half2 a0A = h2z, a1A = h2z, a0B = h2z, a1B = h2z;
#pragma unroll
            for (int i = 0; i < 16; i++) {
                const int eA = e4base + i;
                const int eB = eA + 16;
                uint4 wA = d_Wh4[eA * 512 + jp];
                uint4 wB = d_Wh4[eB * 512 + jp];
                uint2 hA = hhp[eA], hB = hhp[eB];
                a0A = __hfma2(u2h2(wA.x), u2h2(hA.x), a0A);
                a0A = __hfma2(u2h2(wA.y), u2h2(hA.y), a0A);
                a1A = __hfma2(u2h2(wA.z), u2h2(hA.x), a1A);
                a1A = __hfma2(u2h2(wA.w), u2h2(hA.y), a1A);
                a0B = __hfma2(u2h2(wB.x), u2h2(hB.x), a0B);
                a0B = __hfma2(u2h2(wB.y), u2h2(hB.y), a0B);
                a1B = __hfma2(u2h2(wB.z), u2h2(hB.x), a1B);
                a1B = __hfma2(u2h2(wB.w), u2h2(hB.y), a1B);
            }
            float2 f;
            f = __half22float2(a0A); g0 += f.x + f.y;
            f = __half22float2(a1A); g1 += f.x + f.y;
            f = __half22float2(a0B); g0 += f.x + f.y;
            f = __half22float2(a1B); g1 += f.x + f.y;

            if (kq == 1) {
                // U·alpha in fp32, two chains
                float g0b = 0.f, g1b = 0.f;
#pragma unroll
                for (int q4 = 0; q4 < 8; q4++) {
                    uint4 wA = u4b[q4 * 512 + jp];
                    uint4 wB = u4b[(q4 + 8) * 512 + jp];
                    float4 avA = *(const float4*)&alpha_s[4 * q4];
                    float4 avB = *(const float4*)&alpha_s[4 * (q4 + 8)];
                    float2 p;
                    p = h22f2(wA.x); g0  += avA.x * p.x + avA.y * p.y;
                    p = h22f2(wA.y); g0  += avA.z * p.x + avA.w * p.y;
                    p = h22f2(wA.z); g1  += avA.x * p.x + avA.y * p.y;
                    p = h22f2(wA.w); g1  += avA.z * p.x + avA.w * p.y;
                    p = h22f2(wB.x); g0b += avB.x * p.x + avB.y * p.y;
                    p = h22f2(wB.y); g0b += avB.z * p.x + avB.w * p.y;
                    p = h22f2(wB.z); g1b += avB.x * p.x + avB.y * p.y;
                    p = h22f2(wB.w); g1b += avB.z * p.x + avB.w * p.y;
                }
                g0 += g0b; g1 += g1b;
            }
            gpart[kq][tl] = make_float2(g0, g1);
        }
        __syncthreads();

        // combine partials, write local + peer gates
        if (tid < 256) {
            float2 pa = gpart[0][tl], pb = gpart[1][tl];
            float g0 = gp_pre.x + pa.x + pb.x;
            float g1 = gp_pre.y + pa.y + pb.y;
            gates_s[2 * jp]     = g0;
            gates_s[2 * jp + 1] = g1;
            stc_f32x2(gates_peer + (2 * jp) * 4, g0, g1);
        }
        CLUSTER_SYNC();   // #2: full gate vector in both CTAs

        // ---- phase 5: redundant LSTM pointwise (h,c stay replicated) ----
        if (tid < Dh) {
            float ig = gates_s[tid];
            float fg = gates_s[Dh + tid];
            float gg = gates_s[2 * Dh + tid];
            float og = gates_s[3 * Dh + tid];
            float cn = sigmoidf_(fg) * c_s[tid] + sigmoidf_(ig) * tanhf(gg);
            float hn = sigmoidf_(og) * tanhf(cn);
            c_s[tid] = cn;
            h_s[tid] = hn;
            h_h[tid] = __float2half_rn(hn);
            if ((tid >> 7) == r)
                out[((long)t * Bn + b) * Dh + tid] = hn;
        }
        __syncthreads();
    }
}

// ---------------- launch: 4 kernels (front, gp, u, seq) ----------------
extern "C" void kernel_launch(void* const* d_in, const int* in_sizes, int n_in,
                              void* d_out, int out_size)
{
    const float* H_p     = (const float*)d_in[0];
    const float* h_ri    = (const float*)d_in[1];
    const float* H_q     = (const float*)d_in[2];
    const float* hidden  = (const float*)d_in[3];
    const float* Wa      = (const float*)d_in[4];
    const float* ba      = (const float*)d_in[5];
    const float* Wb      = (const float*)d_in[6];
    const float* Wg      = (const float*)d_in[7];
    const float* alpha_w = (const float*)d_in[8];
    const float* alpha_b = (const float*)d_in[9];
    const float* W_ih    = (const float*)d_in[10];
    const float* W_hh    = (const float*)d_in[11];
    const float* b_ih    = (const float*)d_in[12];
    const float* b_hh    = (const float*)d_in[13];
    float* out = (float*)d_out;

    k_front<<<640, 256>>>(b_ih, b_hh, W_hh, Wb, H_q, Wg, H_p, Wa, ba);
    k_gemm_gp<<<dim3(FOUR_D / 128, (Pn * Bn) / 128), 256>>>(H_p, W_ih);
    k_gemm_u<<<dim3(FOUR_D / 64, 1, Qn), 256>>>(H_q, W_ih);
    seq_kernel<<<2 * Bn, 512>>>(h_ri, hidden, alpha_w, alpha_b, out);
}